// round 17
// baseline (speedup 1.0000x reference)
#include <cuda_runtime.h>
#include <cuda_fp16.h>
#include <cstdint>

#define EPSILON_F 1e-9f
#define NQ 100
#define L_SEQ 512
#define THREADS 768               // 24 warps; reg ceiling 84/thr
#define DEPTH 3
#define PF_DIST 8                 // prefetch-to-L2 distance (rows, per warp)
#define ROW_BYTES 2048

// fp16 copy of eta, produced once per launch by convert_kernel
__device__ __align__(16) __half g_eta_h[131072];

__device__ __forceinline__ uint32_t smem_u32(const void* p) {
    uint32_t a;
    asm("{ .reg .u64 t; cvta.to.shared.u64 t, %1; cvt.u32.u64 %0, t; }"
        : "=r"(a) : "l"(p));
    return a;
}
__device__ __forceinline__ void mbar_init(uint32_t m, uint32_t cnt) {
    asm volatile("mbarrier.init.shared.b64 [%0], %1;" :: "r"(m), "r"(cnt) : "memory");
}
__device__ __forceinline__ void mbar_expect_tx(uint32_t m, uint32_t bytes) {
    asm volatile("mbarrier.arrive.expect_tx.shared.b64 _, [%0], %1;"
                 :: "r"(m), "r"(bytes) : "memory");
}
__device__ __forceinline__ void mbar_wait(uint32_t m, uint32_t parity) {
    asm volatile(
        "{\n\t.reg .pred P;\n\t"
        "LW_%=:\n\t"
        "mbarrier.try_wait.parity.acquire.cta.shared::cta.b64 P, [%0], %1, 0x989680;\n\t"
        "@P bra LD_%=;\n\t"
        "bra LW_%=;\n\t"
        "LD_%=:\n\t}"
        :: "r"(m), "r"(parity) : "memory");
}
__device__ __forceinline__ void bulk_g2s(uint32_t dst, const void* src,
                                         uint32_t bytes, uint32_t mbar) {
    asm volatile(
        "cp.async.bulk.shared::cluster.global.mbarrier::complete_tx::bytes "
        "[%0], [%1], %2, [%3];"
        :: "r"(dst), "l"(src), "r"(bytes), "r"(mbar) : "memory");
}

__global__ void convert_kernel(const float* __restrict__ eta, int V) {
    const int n2 = V >> 1;
    const float2* e2 = reinterpret_cast<const float2*>(eta);
    __half2* d2 = reinterpret_cast<__half2*>(g_eta_h);
    const int i = blockIdx.x * blockDim.x + threadIdx.x;
    if (i < n2) {
        float2 v = __ldg(e2 + i);
        d2[i] = __floats2half2_rn(v.x, v.y);
    }
    if (i == 0 && (V & 1))
        g_eta_h[V - 1] = __float2half_rn(__ldg(eta + V - 1));
}

// Persistent: 1 CTA/SM, 24 warps, depth-3 ring, fp16 table via one
// cp.async.bulk, L2 prefetch 8 rows ahead. NEW: refill-FIRST stage order —
// each stage refills the buffer consumed in the PREVIOUS stage at the top
// of the stage, so refill LDGs + prefetch enter the MIO queue BEFORE the
// 16-deep LDS burst instead of trailing it.
__global__ __launch_bounds__(THREADS, 1)
void gather_kernel(const int* __restrict__ idx,
                   const float* __restrict__ t_ptr,
                   float* __restrict__ out, int B, int V) {
    extern __shared__ __align__(16) unsigned char smem[];

    const uint32_t TBL = (uint32_t)((2 * V + 15) & ~15);
    __half* tbl = reinterpret_cast<__half*>(smem);
    float*  ws  = reinterpret_cast<float*>(smem + TBL);

    const uint32_t sbase = smem_u32(smem);
    const uint32_t m_tbl = sbase + TBL + 64;

    const int tid    = threadIdx.x;
    const int warp   = tid >> 5;
    const int lane   = tid & 31;
    const int warps  = blockDim.x >> 5;           // 24
    const int stride = gridDim.x * warps;

    const float t = __ldg(t_ptr);
    const char* ibase = reinterpret_cast<const char*>(idx);

    if (tid == 0) mbar_init(m_tbl, 1);

    const int row0 = blockIdx.x * warps + warp;
    const long step_bytes = (long)stride * ROW_BYTES;

    // ---- prologue: issue DEPTH rows' index loads EARLY ----
    int4 buf0[4], buf1[4], buf2[4];
    #define PROLOAD(BUF, K)                                                   \
    {                                                                         \
        const int r = row0 + (K) * stride;                                    \
        if (r < B) {                                                          \
            const int4* p = reinterpret_cast<const int4*>(                    \
                ibase + (size_t)r * ROW_BYTES);                               \
            _Pragma("unroll")                                                 \
            for (int j = 0; j < 4; j++) BUF[j] = __ldcs(&p[j * 32 + lane]);   \
        }                                                                     \
    }
    PROLOAD(buf0, 0)
    PROLOAD(buf1, 1)
    PROLOAD(buf2, 2)
    #undef PROLOAD

    // prefetch rows DEPTH..PF_DIST-1 to L2 (lead for the first refills)
    for (int k = DEPTH; k < PF_DIST; k++) {
        const long r = (long)row0 + (long)k * stride;
        if (r < B) {
            const char* pp = ibase + r * ROW_BYTES + (lane << 6);
            asm volatile("prefetch.global.L2 [%0];" :: "l"(pp));
        }
    }

    // ---- scalar part: trapz(exp(-E),E), warps 0-3 ----
    if (tid < 128) {
        float val = 0.0f;
        if (tid < NQ - 1) {
            float Ei = ((float)tid       * (1.0f / (NQ - 1))) * t;
            float Ej = ((float)(tid + 1) * (1.0f / (NQ - 1))) * t;
            val = 0.5f * (__expf(-Ei) + __expf(-Ej)) * (Ej - Ei);
        }
        #pragma unroll
        for (int off = 16; off; off >>= 1)
            val += __shfl_xor_sync(0xffffffffu, val, off);
        if (lane == 0) ws[warp] = val;
    }
    __syncthreads();                               // mbar init + ws visible

    // ---- one bulk copy brings the whole fp16 table into smem ----
    if (tid == 0) {
        mbar_expect_tx(m_tbl, TBL);
        bulk_g2s(sbase, g_eta_h, TBL, m_tbl);
    }

    const float base = (ws[0] + ws[1] + ws[2] + ws[3])
                     - 0.5f * t * logf(t + EPSILON_F);

    mbar_wait(m_tbl, 0);                           // table ready

    if (row0 >= B) return;
    int row = row0;

    // gather + reduce + store for CONS (no refill)
    #define CONSUME(BUF)                                                      \
    {                                                                         \
        float a = 0.0f, b = 0.0f, c = 0.0f, d = 0.0f;                         \
        _Pragma("unroll")                                                     \
        for (int j = 0; j < 4; j++) {                                         \
            a += __half2float(tbl[BUF[j].x]);                                 \
            b += __half2float(tbl[BUF[j].y]);                                 \
            c += __half2float(tbl[BUF[j].z]);                                 \
            d += __half2float(tbl[BUF[j].w]);                                 \
        }                                                                     \
        float s = (a + b) + (c + d);                                          \
        _Pragma("unroll")                                                     \
        for (int off = 16; off; off >>= 1)                                    \
            s += __shfl_xor_sync(0xffffffffu, s, off);                        \
        if (lane == 0) out[row] = s + base;                                   \
    }

    // ---- peeled stage 0: consume buf0 (no refill slot free yet) ----
    {
        const long pf = (long)row + (long)PF_DIST * stride;
        if (pf < B) {
            const char* pp = ibase + pf * ROW_BYTES + (lane << 6);
            asm volatile("prefetch.global.L2 [%0];" :: "l"(pp));
        }
        CONSUME(buf0);
        row += stride;
        if (row >= B) return;
    }

    // pointer-increment state; at stage k (>=1) refill target = row+2*stride
    const char* re_ptr = ibase + ((long)row + 2L * stride) * ROW_BYTES
                       + ((uint32_t)lane << 4);
    const char* pf_ptr = ibase + ((long)row + (long)PF_DIST * stride) * ROW_BYTES
                       + ((uint32_t)lane << 6);

    // steady stage: REFILL previous stage's buffer FIRST, prefetch, then
    // consume CONS. Refill row = row + 2*stride (feeds stage k+2).
    #define STAGE(CONS, REF)                                                  \
    {                                                                         \
        if (row + 2 * stride < B) {                                           \
            _Pragma("unroll")                                                 \
            for (int j = 0; j < 4; j++)                                       \
                REF[j] = __ldcs(reinterpret_cast<const int4*>(                \
                    re_ptr + j * 512));                                       \
        }                                                                     \
        if (row + PF_DIST * stride < B)                                       \
            asm volatile("prefetch.global.L2 [%0];" :: "l"(pf_ptr));          \
        re_ptr += step_bytes;                                                 \
        pf_ptr += step_bytes;                                                 \
        CONSUME(CONS);                                                        \
    }

    for (;;) {
        STAGE(buf1, buf0); row += stride; if (row >= B) break;
        STAGE(buf2, buf1); row += stride; if (row >= B) break;
        STAGE(buf0, buf2); row += stride; if (row >= B) break;
    }
    #undef STAGE
    #undef CONSUME
}

extern "C" void kernel_launch(void* const* d_in, const int* in_sizes, int n_in,
                              void* d_out, int out_size) {
    const int*   idx = (const int*)d_in[0];     // [B, 512] int32
    const float* eta = (const float*)d_in[1];   // [V] f32
    const float* t   = (const float*)d_in[2];   // scalar f32
    float* out = (float*)d_out;

    const int B = in_sizes[0] / L_SEQ;
    const int V = in_sizes[1];

    // one-wave convert: ceil((V/2)/256) blocks
    const int cb = ((V >> 1) + 255) / 256;
    convert_kernel<<<cb, 256>>>(eta, V);

    int dev = 0, sms = 148;
    cudaGetDevice(&dev);
    cudaDeviceGetAttribute(&sms, cudaDevAttrMultiProcessorCount, dev);

    const size_t TBL = (size_t)((2 * V + 15) & ~15);
    const size_t smem = TBL + 64 + 64;           // table + ws + mbar
    cudaFuncSetAttribute(gather_kernel,
                         cudaFuncAttributeMaxDynamicSharedMemorySize, (int)smem);

    gather_kernel<<<sms, THREADS, smem>>>(idx, t, out, B, V);
}